// round 17
// baseline (speedup 1.0000x reference)
#include <cuda_runtime.h>
#include <math.h>

#define N_ATOMS 10000
#define N_PAIRS 320000
#define CC 64

typedef unsigned long long ull;

// ---------------- f32x2 helpers (Blackwell packed fp32) ----------------
__device__ __forceinline__ ull pack2(float x) {
    ull r; asm("mov.b64 %0, {%1, %1};" : "=l"(r) : "f"(x)); return r;
}
__device__ __forceinline__ void fma2(ull& acc, ull a, ull b) {
    asm("fma.rn.f32x2 %0, %1, %2, %0;" : "+l"(acc) : "l"(a), "l"(b));
}
__device__ __forceinline__ float2 unpack2(ull v) {
    float2 f; asm("mov.b64 {%0, %1}, %2;" : "=f"(f.x), "=f"(f.y) : "l"(v)); return f;
}
__device__ __forceinline__ float tanh_fast(float x) {
    float y; asm("tanh.approx.f32 %0, %1;" : "=f"(y) : "f"(x)); return y;
}

// ---------------- scratch (device globals; no allocation allowed) ----------------
__device__ float g_p1in[N_ATOMS * 64];
__device__ float g_v[N_ATOMS * 3];
__device__ float g_p1scat[N_ATOMS * 128];
__device__ float g_p3acc[N_ATOMS * 192];
__device__ float g_piWn[2 * 10 * 64 * 64];       // [z][b][k][c]
__device__ float g_A[N_ATOMS * 640];             // p1in @ Wtop + pib   [atom][b][c] f32
__device__ float g_B[N_ATOMS * 640];             // p1in @ Wbot         [atom][b][c] f32
__device__ int   g_cnt[N_ATOMS];
__device__ int   g_woff[N_ATOMS];
__device__ int   g_perm[N_PAIRS];

// ---------------- side stream for fork-join overlap ----------------
struct SideStream {
    cudaStream_t s = nullptr;
    cudaEvent_t fork = nullptr, join = nullptr;
    SideStream() {
        if (cudaStreamCreateWithFlags(&s, cudaStreamNonBlocking) != cudaSuccess) { s = nullptr; return; }
        if (cudaEventCreateWithFlags(&fork, cudaEventDisableTiming) != cudaSuccess) { s = nullptr; return; }
        if (cudaEventCreateWithFlags(&join, cudaEventDisableTiming) != cudaSuccess) { s = nullptr; return; }
    }
};
static SideStream g_ss;

// ---------------- kernel 0: zero scratch ----------------
__global__ void zero_kernel() {
    int idx = blockIdx.x * blockDim.x + threadIdx.x;
    if (idx < N_ATOMS * 3)   g_v[idx] = 0.0f;
    if (idx < N_ATOMS * 128) g_p1scat[idx] = 0.0f;
    if (idx < N_ATOMS * 192) g_p3acc[idx] = 0.0f;
    if (idx < N_ATOMS)       g_cnt[idx] = 0;
}

// ---------------- kernel A: fused count + v accumulation ----------------
__global__ void count_vacc_kernel(const int* __restrict__ ind2,
                                  const float* __restrict__ d3,
                                  const float* __restrict__ fc) {
    int p = blockIdx.x * blockDim.x + threadIdx.x;
    if (p >= N_PAIRS) return;
    int i = ind2[2 * p];
    atomicAdd(&g_cnt[i], 1);
    float f = fc[p];
    atomicAdd(&g_v[i * 3 + 0], d3[p * 3 + 0] * f);
    atomicAdd(&g_v[i * 3 + 1], d3[p * 3 + 1] * f);
    atomicAdd(&g_v[i * 3 + 2], d3[p * 3 + 2] * f);
}

// ---------------- kernel B: exclusive scan (1 block, 1024 thr) ----------------
__global__ void scan_kernel() {
    __shared__ int warp_sums[32];
    __shared__ int carry;
    int tid = threadIdx.x;
    int lane = tid & 31, wid = tid >> 5;
    if (tid == 0) carry = 0;
    __syncthreads();
    for (int base = 0; base < N_ATOMS; base += 1024) {
        int idx = base + tid;
        int v = (idx < N_ATOMS) ? g_cnt[idx] : 0;
        int x = v;
        #pragma unroll
        for (int off = 1; off < 32; off <<= 1) {
            int t = __shfl_up_sync(0xffffffffu, x, off);
            if (lane >= off) x += t;
        }
        if (lane == 31) warp_sums[wid] = x;
        __syncthreads();
        if (wid == 0) {
            int s = warp_sums[lane];
            #pragma unroll
            for (int off = 1; off < 32; off <<= 1) {
                int t = __shfl_up_sync(0xffffffffu, s, off);
                if (lane >= off) s += t;
            }
            warp_sums[lane] = s;
        }
        __syncthreads();
        int excl = carry + (wid > 0 ? warp_sums[wid - 1] : 0) + (x - v);
        if (idx < N_ATOMS) g_woff[idx] = excl;
        __syncthreads();
        if (tid == 0) carry += warp_sums[31];
        __syncthreads();
    }
}

__global__ void scatter_kernel(const int* __restrict__ ind2) {
    int p = blockIdx.x * blockDim.x + threadIdx.x;
    if (p >= N_PAIRS) return;
    int pos = atomicAdd(&g_woff[ind2[2 * p]], 1);
    g_perm[pos] = p;
}

// ---------------- kernel 0b: reorder piW into [z][b][k][c] ----------------
__global__ void prep_kernel(const float* __restrict__ piW) {
    int idx = blockIdx.x * blockDim.x + threadIdx.x;
    if (idx >= 2 * 10 * 64 * 64) return;
    int c  = idx & 63;
    int k  = (idx >> 6) & 63;
    int zb = idx >> 12;
    int z  = zb / 10, b = zb % 10;
    g_piWn[idx] = piW[(z * 64 + k) * 640 + c * 10 + b];
}

// ---------------- kernel 1: p1_in = tanh(tanh(p1@W1+b1)@W2+b2) ----------------
__global__ void p1in_kernel(const float* __restrict__ p1,
                            const float* __restrict__ W1, const float* __restrict__ b1,
                            const float* __restrict__ W2, const float* __restrict__ b2) {
    __shared__ float W1s[4096], W2s[4096], b1s[64], b2s[64];
    __shared__ float xr[4 * 64], hs[4 * 64];
    int tid = threadIdx.x;
    for (int idx = tid; idx < 4096; idx += 256) { W1s[idx] = W1[idx]; W2s[idx] = W2[idx]; }
    if (tid < 64) { b1s[tid] = b1[tid]; b2s[tid] = b2[tid]; }
    int slot = tid >> 6, c = tid & 63;
    int a = blockIdx.x * 4 + slot;
    xr[slot * 64 + c] = p1[a * 64 + c];
    __syncthreads();
    float h = b1s[c];
    #pragma unroll 8
    for (int k = 0; k < 64; ++k) h += xr[slot * 64 + k] * W1s[k * 64 + c];
    hs[slot * 64 + c] = tanhf(h);
    __syncthreads();
    float o = b2s[c];
    #pragma unroll 8
    for (int k = 0; k < 64; ++k) o += hs[slot * 64 + k] * W2s[k * 64 + c];
    g_p1in[a * 64 + c] = tanhf(o);
}

// ---------------- kernel 1b: A/B builder — f32x2 GEMM, atom-pair packing ----------
// grid (79, 20). Block: 128 atoms x 64 channels. lane owns channels (lane, lane+32),
// acc packs ATOM pairs (so no per-atom splat MOVs; 2 weight splats per k instead).
#define AB_SMEM_FLOATS 12544
__global__ __launch_bounds__(256) void ab_kernel(const float* __restrict__ pib) {
    extern __shared__ float absm[];
    float* xs = absm;            // [k][atom] stride 132
    float* Wb = absm + 8448;     // [k][c]
    int tid = threadIdx.x;
    int zb = blockIdx.y, z = zb / 10, b = zb % 10;
    int abase = blockIdx.x * 128;

    for (int idx = tid; idx < 4096; idx += 256) Wb[idx] = g_piWn[zb * 4096 + idx];
    {
        int k = tid & 63, a0 = tid >> 6;
        #pragma unroll 8
        for (int r = 0; r < 32; ++r) {
            int a = a0 + r * 4;
            int ga = abase + a;
            xs[k * 132 + a] = (ga < N_ATOMS) ? g_p1in[ga * 64 + k] : 0.0f;
        }
    }
    __syncthreads();

    int lane = tid & 31, wg = tid >> 5;
    int ch0 = lane, ch1 = lane + 32;
    ull bias0 = 0ULL, bias1 = 0ULL;
    if (z == 0) { bias0 = pack2(pib[ch0 * 10 + b]); bias1 = pack2(pib[ch1 * 10 + b]); }
    ull acc0[8], acc1[8];        // [atom-pair] for ch0 / ch1
    #pragma unroll
    for (int r = 0; r < 8; ++r) { acc0[r] = bias0; acc1[r] = bias1; }

    const float* xw = xs + wg * 16;
    #pragma unroll 2
    for (int k = 0; k < 64; ++k) {
        float4 q0 = *(const float4*)(xw + k * 132);        // atoms 0-3   (2 ull pairs)
        float4 q1 = *(const float4*)(xw + k * 132 + 4);    // atoms 4-7
        float4 q2 = *(const float4*)(xw + k * 132 + 8);    // atoms 8-11
        float4 q3 = *(const float4*)(xw + k * 132 + 12);   // atoms 12-15
        ull W0 = pack2(Wb[k * 64 + ch0]);
        ull W1 = pack2(Wb[k * 64 + ch1]);
        const ull* xp0 = (const ull*)&q0;
        const ull* xp1 = (const ull*)&q1;
        const ull* xp2 = (const ull*)&q2;
        const ull* xp3 = (const ull*)&q3;
        fma2(acc0[0], xp0[0], W0); fma2(acc1[0], xp0[0], W1);
        fma2(acc0[1], xp0[1], W0); fma2(acc1[1], xp0[1], W1);
        fma2(acc0[2], xp1[0], W0); fma2(acc1[2], xp1[0], W1);
        fma2(acc0[3], xp1[1], W0); fma2(acc1[3], xp1[1], W1);
        fma2(acc0[4], xp2[0], W0); fma2(acc1[4], xp2[0], W1);
        fma2(acc0[5], xp2[1], W0); fma2(acc1[5], xp2[1], W1);
        fma2(acc0[6], xp3[0], W0); fma2(acc1[6], xp3[0], W1);
        fma2(acc0[7], xp3[1], W0); fma2(acc1[7], xp3[1], W1);
    }

    float* out = z ? g_B : g_A;
    #pragma unroll
    for (int r = 0; r < 8; ++r) {
        int a0 = abase + wg * 16 + 2 * r;
        int a1 = a0 + 1;
        float2 v0 = unpack2(acc0[r]);   // (atom a0, atom a1) for ch0
        float2 v1 = unpack2(acc1[r]);   // for ch1
        if (a0 < N_ATOMS) {
            out[(size_t)a0 * 640 + b * 64 + ch0] = v0.x;
            out[(size_t)a0 * 640 + b * 64 + ch1] = v1.x;
        }
        if (a1 < N_ATOMS) {
            out[(size_t)a1 * 640 + b * 64 + ch0] = v0.y;
            out[(size_t)a1 * 640 + b * 64 + ch1] = v1.y;
        }
    }
}

// ---------------- kernel 3: main per-pair kernel (sorted pairs, 3 CTAs/SM) ----------------
// smem (floats):
//   Z    [0,     8256)   64x129 (z vectors; [64:128] = gate)
//   sIp  [8256,  12416)  64x65 i_pair
//   Ws   [12416, 16512)  iiW half-chunk 64x64
//   sB   [16512, 17152)  basis 64x10
//   sD3  [17152, 17344)  sFc [17344, 17408)
//   sI/sJ[17408, 17536)
//   sGeo [17536, 17792)  64x4 (t3x,t3y,t3z,tb)
//   sPm  [17792, 17856)  int x64
#define PAIR_SMEM_FLOATS 17856
__global__ __launch_bounds__(256, 3) void pair_kernel(
                            const int* __restrict__ ind2,
                            const float* __restrict__ p3,
                            const float* __restrict__ basis,
                            const float* __restrict__ d3,
                            const float* __restrict__ fc,
                            const float* __restrict__ iiW) {
    extern __shared__ float sm[];
    float* Z     = sm;
    float* sIp   = sm + 8256;
    float* Ws    = sm + 12416;
    float* sB    = sm + 16512;
    float* sD3   = sm + 17152;
    float* sFc   = sm + 17344;
    int*   sI    = (int*)(sm + 17408);
    int*   sJ    = sI + 64;
    float* sGeo  = sm + 17536;
    int*   sPm   = (int*)(sm + 17792);

    int tid = threadIdx.x;
    int lane = tid & 31;
    int wg   = tid >> 5;
    int pbase = blockIdx.x * 64;

    if (tid < 64) {
        int pm = g_perm[pbase + tid];
        sPm[tid] = pm;
        sI[tid]  = ind2[2 * pm];
        sJ[tid]  = ind2[2 * pm + 1];
        sFc[tid] = fc[pm];
    }
    __syncthreads();
    for (int idx = tid; idx < 640; idx += 256) {
        int m = idx / 10, b = idx - 10 * m;
        sB[idx] = basis[(size_t)sPm[m] * 10 + b];
    }
    for (int idx = tid; idx < 192; idx += 256) {
        int m = idx / 3, r = idx - 3 * m;
        sD3[idx] = d3[(size_t)sPm[m] * 3 + r];
    }
    __syncthreads();

    // ---- stage 1: i_pair[m][c] = sum_b tanh(A[i]+B[j]) * basis
    {
        int rh = lane >> 4;          // 0/1
        int q  = lane & 15;          // channel quad (4 ch)
        #pragma unroll
        for (int it = 0; it < 4; ++it) {
            int m = wg * 8 + it * 2 + rh;
            const float4* Ai = (const float4*)(g_A + (size_t)sI[m] * 640) + q;
            const float4* Bj = (const float4*)(g_B + (size_t)sJ[m] * 640) + q;
            float s0 = 0.0f, s1 = 0.0f, s2 = 0.0f, s3 = 0.0f;
            #pragma unroll
            for (int half = 0; half < 2; ++half) {
                float4 a4[5], b4[5];
                #pragma unroll
                for (int b5 = 0; b5 < 5; ++b5) {
                    int b = half * 5 + b5;
                    a4[b5] = Ai[b * 16];
                    b4[b5] = Bj[b * 16];
                }
                #pragma unroll
                for (int b5 = 0; b5 < 5; ++b5) {
                    float bas = sB[m * 10 + half * 5 + b5];
                    s0 += tanh_fast(a4[b5].x + b4[b5].x) * bas;
                    s1 += tanh_fast(a4[b5].y + b4[b5].y) * bas;
                    s2 += tanh_fast(a4[b5].z + b4[b5].z) * bas;
                    s3 += tanh_fast(a4[b5].w + b4[b5].w) * bas;
                }
            }
            int c0 = q * 4;
            sIp[m * 65 + c0]     = s0;
            sIp[m * 65 + c0 + 1] = s1;
            sIp[m * 65 + c0 + 2] = s2;
            sIp[m * 65 + c0 + 3] = s3;
        }
    }

    // ---- stage 2: z = tanh(i_pair @ iiW) (64->128), iiW in 2 col-chunks of 64 ----
    #pragma unroll
    for (int cc = 0; cc < 2; ++cc) {
        __syncthreads();
        for (int idx = tid; idx < 4096; idx += 256) {
            int k = idx >> 6, cl = idx & 63;
            Ws[idx] = iiW[k * 128 + cc * 64 + cl];
        }
        __syncthreads();
        int n0 = wg * 8;
        ull z0[4], z1[4];
        #pragma unroll
        for (int t = 0; t < 4; ++t) { z0[t] = 0ULL; z1[t] = 0ULL; }
        const float* ir0 = sIp + lane * 65;
        const float* ir1 = sIp + (lane + 32) * 65;
        #pragma unroll 4
        for (int k = 0; k < 64; ++k) {
            ull A0 = pack2(ir0[k]);
            ull A1 = pack2(ir1[k]);
            const ull* qp = (const ull*)(Ws + k * 64 + n0);
            #pragma unroll
            for (int t = 0; t < 4; ++t) {
                ull w = qp[t];
                fma2(z0[t], A0, w);
                fma2(z1[t], A1, w);
            }
        }
        float* zr0 = Z + lane * 129 + cc * 64;
        float* zr1 = Z + (lane + 32) * 129 + cc * 64;
        #pragma unroll
        for (int t = 0; t < 4; ++t) {
            float2 a = unpack2(z0[t]);
            float2 b = unpack2(z1[t]);
            zr0[n0 + 2 * t]     = tanh_fast(a.x);
            zr0[n0 + 2 * t + 1] = tanh_fast(a.y);
            zr1[n0 + 2 * t]     = tanh_fast(b.x);
            zr1[n0 + 2 * t + 1] = tanh_fast(b.y);
        }
    }
    __syncthreads();

    // ---- stage 3a: per-pair geometry ----
    if (tid < 64) {
        int m = tid;
        int i = sI[m];
        float fcv = sFc[m];
        float dx = sD3[m * 3 + 0], dy = sD3[m * 3 + 1], dz = sD3[m * 3 + 2];
        float vx = g_v[i * 3 + 0], vy = g_v[i * 3 + 1], vz = g_v[i * 3 + 2];
        float proj = vx * dx + vy * dy + vz * dz;
        float wx = vx - proj * dx, wy = vy - proj * dy, wzc = vz - proj * dz;
        float w2 = wx * wx + wy * wy + wzc * wzc;
        float gdeg = w2 / (w2 + 1e-4f);
        float rs = rsqrtf(w2 + 1e-6f);
        float sc = rs * gdeg;
        sGeo[m * 4 + 0] = wx * sc;
        sGeo[m * 4 + 1] = wy * sc;
        sGeo[m * 4 + 2] = wzc * sc;
        sGeo[m * 4 + 3] = gdeg * fcv * fcv;
    }
    __syncthreads();

    // ---- stage 3: fused segmented reduction, p3 contributions computed on the fly ----
    {
        bool isP1 = (tid < 128);
        int ch = isP1 ? tid : (tid - 128);
        int r  = ch >> 6, cl = ch & 63;
        float acc = 0.0f;
        if (isP1) {
            const float* src = Z + ch;
            #pragma unroll 8
            for (int m = 0; m < 64; ++m) {
                acc += src[m * 129];
                if (m == 63 || sI[m + 1] != sI[m]) {
                    atomicAdd(g_p1scat + (size_t)sI[m] * 128 + ch, acc);
                    acc = 0.0f;
                }
            }
        } else {
            #pragma unroll 4
            for (int m = 0; m < 64; ++m) {
                float g = Z[m * 129 + 64 + cl];
                float pj = p3[(size_t)sJ[m] * 192 + r * 64 + cl];
                acc += pj * g + sD3[m * 3 + r] * g + sGeo[m * 4 + r] * (g * sGeo[m * 4 + 3]);
                if (m == 63 || sI[m + 1] != sI[m]) {
                    atomicAdd(g_p3acc + (size_t)sI[m] * 192 + r * 64 + cl, acc);
                    acc = 0.0f;
                }
            }
        }
    }
    if (tid < 64) {
        int cl = tid;
        float acc = 0.0f;
        #pragma unroll 4
        for (int m = 0; m < 64; ++m) {
            float g = Z[m * 129 + 64 + cl];
            float pj = p3[(size_t)sJ[m] * 192 + 128 + cl];
            acc += pj * g + sD3[m * 3 + 2] * g + sGeo[m * 4 + 2] * (g * sGeo[m * 4 + 3]);
            if (m == 63 || sI[m + 1] != sI[m]) {
                atomicAdd(g_p3acc + (size_t)sI[m] * 192 + 128 + cl, acc);
                acc = 0.0f;
            }
        }
    }
}

// ---------------- kernel 4: atom-side tail, writes d_out ----------------
// grid 250 x 256; each block handles 40 atoms, 4 concurrent (10 iters, exact tiling)
#define FINAL_SMEM_FLOATS 36032
__global__ void atom_final_kernel(const float* __restrict__ postW1,
                                  const float* __restrict__ postW2,
                                  const float* __restrict__ eqW,
                                  const float* __restrict__ q1W,
                                  const float* __restrict__ q1b,
                                  const float* __restrict__ q2W,
                                  const float* __restrict__ q2b,
                                  float* __restrict__ out) {
    extern __shared__ float sm[];
    float* W1s  = sm;
    float* W2s  = sm + 8192;
    float* Es   = sm + 12288;
    float* Q1s  = sm + 16384;
    float* Q2s  = sm + 24576;
    float* b1s  = sm + 32768;
    float* b2s  = sm + 32832;
    float* ps   = sm + 32960;
    float* p3a  = sm + 33472;
    float* sH   = sm + 34240;
    float* sP1  = sm + 34496;
    float* sP3n = sm + 34752;
    float* sD   = sm + 35520;
    float* sH2  = sm + 35776;

    int tid = threadIdx.x;
    for (int idx = tid; idx < 8192; idx += 256) W1s[idx] = postW1[idx];
    for (int idx = tid; idx < 4096; idx += 256) { W2s[idx] = postW2[idx]; Es[idx] = eqW[idx]; }
    for (int idx = tid; idx < 8192; idx += 256) { Q1s[idx] = q1W[idx]; Q2s[idx] = q2W[idx]; }
    if (tid < 64)  b1s[tid] = q1b[tid];
    if (tid < 128) b2s[tid] = q2b[tid];

    int slot = tid >> 6, c = tid & 63;
    int abase = blockIdx.x * 40;
    for (int it = 0; it < 10; ++it) {
        __syncthreads();
        int a = abase + it * 4 + slot;
        bool valid = (a < N_ATOMS);
        if (valid) {
            ps[slot * 128 + c]       = g_p1scat[a * 128 + c];
            ps[slot * 128 + 64 + c]  = g_p1scat[a * 128 + 64 + c];
            p3a[slot * 192 + c]       = g_p3acc[a * 192 + c];
            p3a[slot * 192 + 64 + c]  = g_p3acc[a * 192 + 64 + c];
            p3a[slot * 192 + 128 + c] = g_p3acc[a * 192 + 128 + c];
        } else {
            ps[slot * 128 + c] = 0.0f; ps[slot * 128 + 64 + c] = 0.0f;
            p3a[slot * 192 + c] = 0.0f; p3a[slot * 192 + 64 + c] = 0.0f;
            p3a[slot * 192 + 128 + c] = 0.0f;
        }
        __syncthreads();
        float h = 0.0f;
        #pragma unroll 8
        for (int k = 0; k < 128; ++k) h += ps[slot * 128 + k] * W1s[k * 64 + c];
        sH[slot * 64 + c] = tanhf(h);
        __syncthreads();
        float o = 0.0f;
        float p0 = 0.0f, p1v = 0.0f, p2 = 0.0f;
        #pragma unroll 8
        for (int k = 0; k < 64; ++k) {
            o += sH[slot * 64 + k] * W2s[k * 64 + c];
            float e = Es[k * 64 + c];
            p0  += p3a[slot * 192 + k]       * e;
            p1v += p3a[slot * 192 + 64 + k]  * e;
            p2  += p3a[slot * 192 + 128 + k] * e;
        }
        sP1[slot * 64 + c] = tanhf(o);
        sP3n[slot * 192 + c]       = p0;
        sP3n[slot * 192 + 64 + c]  = p1v;
        sP3n[slot * 192 + 128 + c] = p2;
        sD[slot * 64 + c] = p0 * p0 + p1v * p1v + p2 * p2;
        __syncthreads();
        float h2 = b1s[c];
        #pragma unroll 8
        for (int k = 0; k < 64; ++k) {
            h2 += sP1[slot * 64 + k] * Q1s[k * 64 + c];
            h2 += sD[slot * 64 + k]  * Q1s[(64 + k) * 64 + c];
        }
        sH2[slot * 64 + c] = tanhf(h2);
        __syncthreads();
        float o1 = b2s[c], o2 = b2s[64 + c];
        #pragma unroll 8
        for (int k = 0; k < 64; ++k) {
            float hh = sH2[slot * 64 + k];
            o1 += hh * Q2s[k * 128 + c];
            o2 += hh * Q2s[k * 128 + 64 + c];
        }
        o1 = tanhf(o1);
        o2 = tanhf(o2);
        if (valid) {
            out[a * 64 + c] = o1;
            float* po = out + N_ATOMS * 64 + (size_t)a * 192;
            po[c]        = sP3n[slot * 192 + c]       * o2;
            po[64 + c]   = sP3n[slot * 192 + 64 + c]  * o2;
            po[128 + c]  = sP3n[slot * 192 + 128 + c] * o2;
        }
    }
}

// ---------------- launch ----------------
extern "C" void kernel_launch(void* const* d_in, const int* in_sizes, int n_in,
                              void* d_out, int out_size) {
    const int*   ind2   = (const int*)d_in[0];
    const float* p1     = (const float*)d_in[1];
    const float* p3     = (const float*)d_in[2];
    const float* basis  = (const float*)d_in[3];
    const float* d3     = (const float*)d_in[4];
    const float* fc     = (const float*)d_in[5];
    const float* preW1  = (const float*)d_in[6];
    const float* preb1  = (const float*)d_in[7];
    const float* preW2  = (const float*)d_in[8];
    const float* preb2  = (const float*)d_in[9];
    const float* piW    = (const float*)d_in[10];
    const float* pib    = (const float*)d_in[11];
    const float* iiW    = (const float*)d_in[12];
    const float* postW1 = (const float*)d_in[13];
    const float* postW2 = (const float*)d_in[14];
    const float* eqW    = (const float*)d_in[15];
    const float* q1W    = (const float*)d_in[16];
    const float* q1b    = (const float*)d_in[17];
    const float* q2W    = (const float*)d_in[18];
    const float* q2b    = (const float*)d_in[19];
    float* out = (float*)d_out;

    cudaFuncSetAttribute(ab_kernel, cudaFuncAttributeMaxDynamicSharedMemorySize,
                         AB_SMEM_FLOATS * 4);
    cudaFuncSetAttribute(pair_kernel, cudaFuncAttributeMaxDynamicSharedMemorySize,
                         PAIR_SMEM_FLOATS * 4);
    cudaFuncSetAttribute(atom_final_kernel, cudaFuncAttributeMaxDynamicSharedMemorySize,
                         FINAL_SMEM_FLOATS * 4);

    dim3 ab_grid((N_ATOMS + 127) / 128, 20, 1);

    if (g_ss.s) {
        cudaEventRecord(g_ss.fork, 0);
        cudaStreamWaitEvent(g_ss.s, g_ss.fork, 0);

        prep_kernel<<<(2 * 10 * 64 * 64 + 255) / 256, 256>>>(piW);
        p1in_kernel<<<N_ATOMS / 4, 256>>>(p1, preW1, preb1, preW2, preb2);
        zero_kernel<<<(N_ATOMS * 192 + 255) / 256, 256, 0, g_ss.s>>>();
        ab_kernel<<<ab_grid, 256, AB_SMEM_FLOATS * 4>>>(pib);
        count_vacc_kernel<<<(N_PAIRS + 255) / 256, 256, 0, g_ss.s>>>(ind2, d3, fc);
        scan_kernel<<<1, 1024, 0, g_ss.s>>>();
        scatter_kernel<<<(N_PAIRS + 255) / 256, 256, 0, g_ss.s>>>(ind2);

        cudaEventRecord(g_ss.join, g_ss.s);
        cudaStreamWaitEvent(0, g_ss.join, 0);
    } else {
        prep_kernel<<<(2 * 10 * 64 * 64 + 255) / 256, 256>>>(piW);
        p1in_kernel<<<N_ATOMS / 4, 256>>>(p1, preW1, preb1, preW2, preb2);
        zero_kernel<<<(N_ATOMS * 192 + 255) / 256, 256>>>();
        ab_kernel<<<ab_grid, 256, AB_SMEM_FLOATS * 4>>>(pib);
        count_vacc_kernel<<<(N_PAIRS + 255) / 256, 256>>>(ind2, d3, fc);
        scan_kernel<<<1, 1024>>>();
        scatter_kernel<<<(N_PAIRS + 255) / 256, 256>>>(ind2);
    }

    pair_kernel<<<N_PAIRS / 64, 256, PAIR_SMEM_FLOATS * 4>>>(ind2, p3, basis, d3, fc, iiW);
    atom_final_kernel<<<250, 256, FINAL_SMEM_FLOATS * 4>>>(postW1, postW2, eqW,
                                                           q1W, q1b, q2W, q2b, out);
}